// round 8
// baseline (speedup 1.0000x reference)
#include <cuda_runtime.h>
#include <cuda_bf16.h>

#define TPB 512
#define EPT 8    // elements per thread per row; TPB*EPT == T == 4096
#define NWARP (TPB / 32)

// idx_mask committed as int32 0/1 flags (verified R7: rel_err==0 + HBM traffic
// matches the int32 footprint). Two rows per CTA; both rows' block-wide
// max-scans are packed into one 32-bit value (local_last in [-1,4095] fits
// s16) and reduced together with __vmaxs2 -> one scan + one barrier for 2 rows.
__global__ __launch_bounds__(TPB, 2) void seg_mask_kernel(
    const float* __restrict__ x,
    const int*   __restrict__ idx_mask,       // [rows*T] int32 0/1
    const int*   __restrict__ mask_size,      // [S]
    const int*   __restrict__ mask_value,     // scalar
    float* __restrict__ out,                  // [rows*T]
    float* __restrict__ mask_out,             // [rows*T] or nullptr
    int S, int T)
{
    const int tid  = threadIdx.x;
    const int lane = tid & 31, wid = tid >> 5;
    const int t0   = tid * EPT;
    const int r0   = blockIdx.x * 2;          // rows r0, r0+1
    const long long base0 = (long long)r0 * T;
    const long long base1 = base0 + T;

    // ---- front-batch ALL loads for both rows (8x LDG.128) ----
    const int4*   ip0 = (const int4*)(idx_mask + base0 + t0);
    const int4*   ip1 = (const int4*)(idx_mask + base1 + t0);
    const float4* xv0 = (const float4*)(x + base0 + t0);
    const float4* xv1 = (const float4*)(x + base1 + t0);
    int4   a0 = __ldcs(ip0 + 0);
    int4   b0 = __ldcs(ip0 + 1);
    int4   a1 = __ldcs(ip1 + 0);
    int4   b1 = __ldcs(ip1 + 1);
    float4 x00 = __ldcs(xv0 + 0);
    float4 x01 = __ldcs(xv0 + 1);
    float4 x10 = __ldcs(xv1 + 0);
    float4 x11 = __ldcs(xv1 + 1);

    unsigned bits0 =
          ((unsigned)(a0.x != 0) << 0) | ((unsigned)(a0.y != 0) << 1)
        | ((unsigned)(a0.z != 0) << 2) | ((unsigned)(a0.w != 0) << 3)
        | ((unsigned)(b0.x != 0) << 4) | ((unsigned)(b0.y != 0) << 5)
        | ((unsigned)(b0.z != 0) << 6) | ((unsigned)(b0.w != 0) << 7);
    unsigned bits1 =
          ((unsigned)(a1.x != 0) << 0) | ((unsigned)(a1.y != 0) << 1)
        | ((unsigned)(a1.z != 0) << 2) | ((unsigned)(a1.w != 0) << 3)
        | ((unsigned)(b1.x != 0) << 4) | ((unsigned)(b1.y != 0) << 5)
        | ((unsigned)(b1.z != 0) << 6) | ((unsigned)(b1.w != 0) << 7);

    const int   m0 = __ldg(mask_size + (r0 % S));
    const int   m1 = __ldg(mask_size + ((r0 + 1) % S));
    const float mv = (float)__ldg(mask_value);

    // ---- local "last start index" per row, packed into s16x2 ----
    int l0 = bits0 ? (t0 + 31 - __clz(bits0)) : -1;
    int l1 = bits1 ? (t0 + 31 - __clz(bits1)) : -1;
    unsigned p = ((unsigned)(l0 & 0xFFFF) << 16) | (unsigned)(l1 & 0xFFFF);

    // ---- single packed block-wide exclusive max-scan (both rows) ----
    #pragma unroll
    for (int off = 1; off < 32; off <<= 1) {
        unsigned u = __shfl_up_sync(0xffffffffu, p, off);
        if (lane >= off) p = __vmaxs2(p, u);
    }
    __shared__ unsigned wmax[NWARP];
    if (lane == 31) wmax[wid] = p;
    __syncthreads();
    unsigned incl_prev = __shfl_up_sync(0xffffffffu, p, 1);
    const unsigned NEG1 = 0xFFFFFFFFu;        // (-1, -1) packed
    unsigned excl = (lane == 0) ? NEG1 : incl_prev;
    #pragma unroll
    for (int w = 0; w < NWARP; w++)
        if (w < wid) excl = __vmaxs2(excl, wmax[w]);

    int excl0 = (int)((short)(excl >> 16));
    int excl1 = (int)((short)(excl & 0xFFFF));

    // ---- compute + store, row 0 then row 1 ----
    {
        float4* ov  = (float4*)(out + base0 + t0);
        float4* mov = mask_out ? (float4*)(mask_out + base0 + t0) : nullptr;
        float4 xr[2] = {x00, x01};
        int cur = excl0;
        #pragma unroll
        for (int j = 0; j < 2; j++) {
            const float* xa = (const float*)&xr[j];
            float o[4], mk[4];
            #pragma unroll
            for (int i = 0; i < 4; i++) {
                int k = j * 4 + i;
                int t = t0 + k;
                if ((bits0 >> k) & 1u) cur = t;
                int lo = t - m0; if (lo < 0) lo = 0;
                bool msk = (cur >= lo);
                mk[i] = msk ? 1.0f : 0.0f;
                o[i]  = msk ? mv : xa[i];
            }
            float4 ot = {o[0], o[1], o[2], o[3]};
            __stcs(ov + j, ot);
            if (mov) { float4 mt = {mk[0], mk[1], mk[2], mk[3]}; __stcs(mov + j, mt); }
        }
    }
    {
        float4* ov  = (float4*)(out + base1 + t0);
        float4* mov = mask_out ? (float4*)(mask_out + base1 + t0) : nullptr;
        float4 xr[2] = {x10, x11};
        int cur = excl1;
        #pragma unroll
        for (int j = 0; j < 2; j++) {
            const float* xa = (const float*)&xr[j];
            float o[4], mk[4];
            #pragma unroll
            for (int i = 0; i < 4; i++) {
                int k = j * 4 + i;
                int t = t0 + k;
                if ((bits1 >> k) & 1u) cur = t;
                int lo = t - m1; if (lo < 0) lo = 0;
                bool msk = (cur >= lo);
                mk[i] = msk ? 1.0f : 0.0f;
                o[i]  = msk ? mv : xa[i];
            }
            float4 ot = {o[0], o[1], o[2], o[3]};
            __stcs(ov + j, ot);
            if (mov) { float4 mt = {mk[0], mk[1], mk[2], mk[3]}; __stcs(mov + j, mt); }
        }
    }
}

extern "C" void kernel_launch(void* const* d_in, const int* in_sizes, int n_in,
                              void* d_out, int out_size) {
    const float* x     = (const float*)d_in[0];
    const int*   idx   = (const int*)d_in[1];
    const int*   msize = (const int*)d_in[2];
    const int*   mval  = (const int*)d_in[3];
    float* out = (float*)d_out;

    const int T = 4096;
    const int N = in_sizes[0];          // B*S*T
    const int S = in_sizes[2];          // 128
    const int rows = N / T;             // B*S = 8192 (even)

    // Tuple output (out, mask) -> concatenated float32 if out_size covers both.
    float* mask_out = (out_size >= 2 * N) ? (out + (long long)N) : nullptr;

    seg_mask_kernel<<<rows / 2, TPB>>>(x, idx, msize, mval, out, mask_out, S, T);
}

// round 9
// speedup vs baseline: 1.0987x; 1.0987x over previous
#include <cuda_runtime.h>
#include <cuda_bf16.h>

#define TPB 512
#define EPT 8    // elements per thread; TPB*EPT == T == 4096
#define NWARP (TPB / 32)

// idx_mask encoding committed as int32 0/1 flags (verified R7: rel_err==0 and
// measured HBM traffic ~536MB matches the int32 footprint; bool would be ~436MB).
// One row per CTA, front-batched .cs loads, single block max-scan, .cs stores.
// R8 lesson: do NOT pack 2 rows/thread (regs 32->48 halves occupancy, -8%% DRAM).
__global__ __launch_bounds__(TPB) void seg_mask_kernel(
    const float* __restrict__ x,
    const int*   __restrict__ idx_mask,       // [rows*T] int32 0/1
    const int*   __restrict__ mask_size,      // [S]
    const int*   __restrict__ mask_value,     // scalar
    float* __restrict__ out,                  // [rows*T]
    float* __restrict__ mask_out,             // [rows*T] or nullptr
    int S, int T)
{
    const int tid  = threadIdx.x;
    const int lane = tid & 31, wid = tid >> 5;
    const int t0   = tid * EPT;
    const int row  = blockIdx.x;              // row = b*S + s
    const int s    = row % S;
    const long long base = (long long)row * T;

    // ---- front-batch ALL loads (flags + x) for max MLP ----
    const int4*   ip = (const int4*)(idx_mask + base + t0);
    const float4* xv = (const float4*)(x + base + t0);
    int4   a  = __ldcs(ip + 0);
    int4   b  = __ldcs(ip + 1);
    float4 xx0 = __ldcs(xv + 0);
    float4 xx1 = __ldcs(xv + 1);

    unsigned bits =
          ((unsigned)(a.x != 0) << 0) | ((unsigned)(a.y != 0) << 1)
        | ((unsigned)(a.z != 0) << 2) | ((unsigned)(a.w != 0) << 3)
        | ((unsigned)(b.x != 0) << 4) | ((unsigned)(b.y != 0) << 5)
        | ((unsigned)(b.z != 0) << 6) | ((unsigned)(b.w != 0) << 7);

    const int   m  = __ldg(mask_size + s);
    const float mv = (float)__ldg(mask_value);

    // ---- local "last start index" within chunk ----
    int v = bits ? (t0 + 31 - __clz(bits)) : -1;

    // ---- block-wide exclusive max-scan ----
    #pragma unroll
    for (int off = 1; off < 32; off <<= 1) {
        int u = __shfl_up_sync(0xffffffffu, v, off);
        if (lane >= off) v = max(v, u);
    }
    __shared__ int wmax[NWARP];
    if (lane == 31) wmax[wid] = v;
    __syncthreads();
    int incl_prev = __shfl_up_sync(0xffffffffu, v, 1);
    int excl = (lane == 0) ? -1 : incl_prev;
    #pragma unroll
    for (int w = 0; w < NWARP; w++)
        if (w < wid) excl = max(excl, wmax[w]);

    // ---- compute out / mask with carried last-start ----
    float4* ov  = (float4*)(out + base + t0);
    float4* mov = mask_out ? (float4*)(mask_out + base + t0) : nullptr;

    float4 xr[2] = {xx0, xx1};
    float4 otv[2], mtv[2];
    int cur = excl;
    #pragma unroll
    for (int j = 0; j < 2; j++) {
        const float* xa = (const float*)&xr[j];
        float o[4], mk[4];
        #pragma unroll
        for (int i = 0; i < 4; i++) {
            int k = j * 4 + i;
            int t = t0 + k;
            if ((bits >> k) & 1u) cur = t;
            int lo = t - m; if (lo < 0) lo = 0;
            bool msk = (cur >= lo);           // cur == -1 always fails (lo >= 0)
            mk[i] = msk ? 1.0f : 0.0f;
            o[i]  = msk ? mv : xa[i];
        }
        otv[j] = make_float4(o[0], o[1], o[2], o[3]);
        mtv[j] = make_float4(mk[0], mk[1], mk[2], mk[3]);
    }
    // Grouped streaming-evict stores: back-to-back bursts per output stream.
    __stcs(ov + 0, otv[0]);
    __stcs(ov + 1, otv[1]);
    if (mov) {
        __stcs(mov + 0, mtv[0]);
        __stcs(mov + 1, mtv[1]);
    }
}

extern "C" void kernel_launch(void* const* d_in, const int* in_sizes, int n_in,
                              void* d_out, int out_size) {
    const float* x     = (const float*)d_in[0];
    const int*   idx   = (const int*)d_in[1];
    const int*   msize = (const int*)d_in[2];
    const int*   mval  = (const int*)d_in[3];
    float* out = (float*)d_out;

    const int T = 4096;
    const int N = in_sizes[0];          // B*S*T
    const int S = in_sizes[2];          // 128
    const int rows = N / T;             // B*S = 8192

    // Tuple output (out, mask) -> concatenated float32 if out_size covers both.
    float* mask_out = (out_size >= 2 * N) ? (out + (long long)N) : nullptr;

    seg_mask_kernel<<<rows, TPB>>>(x, idx, msize, mval, out, mask_out, S, T);
}

// round 10
// speedup vs baseline: 1.1261x; 1.0250x over previous
#include <cuda_runtime.h>
#include <cuda_bf16.h>

#define TPB 512
#define NWARP (TPB / 32)
// Interleaved layout: thread tid owns elements [4*tid, 4*tid+4) of the row's
// first half and [T/2 + 4*tid, ...) of the second half. Lane stride = 16B ->
// every LDG.128/STG.128 wavefront is 512B fully contiguous (full sectors),
// halving L1tex wavefronts vs the blocked layout (R9: 32B lane stride).
// Both halves' max-scans are packed s16x2 and done in ONE block scan
// (__vmaxs2); the second half's carry adds the first half's block total.
// idx_mask committed as int32 0/1 (verified R7 via rel_err + traffic).
__global__ __launch_bounds__(TPB) void seg_mask_kernel(
    const float* __restrict__ x,
    const int*   __restrict__ idx_mask,       // [rows*T] int32 0/1
    const int*   __restrict__ mask_size,      // [S]
    const int*   __restrict__ mask_value,     // scalar
    float* __restrict__ out,                  // [rows*T]
    float* __restrict__ mask_out,             // [rows*T] or nullptr
    int S, int T)
{
    const int tid  = threadIdx.x;
    const int lane = tid & 31, wid = tid >> 5;
    const int row  = blockIdx.x;              // row = b*S + s
    const int s    = row % S;
    const long long base = (long long)row * T;
    const int half = T >> 1;                  // 2048
    const int t0a  = tid * 4;                 // first-half positions
    const int t0b  = half + tid * 4;          // second-half positions

    // ---- front-batch ALL loads, fully coalesced (lane stride 16B) ----
    const int4*   ipa = (const int4*)(idx_mask + base + t0a);
    const int4*   ipb = (const int4*)(idx_mask + base + t0b);
    const float4* xva = (const float4*)(x + base + t0a);
    const float4* xvb = (const float4*)(x + base + t0b);
    int4   ia = __ldcs(ipa);
    int4   ib = __ldcs(ipb);
    float4 xa = __ldcs(xva);
    float4 xb = __ldcs(xvb);

    unsigned bitsa =
          ((unsigned)(ia.x != 0) << 0) | ((unsigned)(ia.y != 0) << 1)
        | ((unsigned)(ia.z != 0) << 2) | ((unsigned)(ia.w != 0) << 3);
    unsigned bitsb =
          ((unsigned)(ib.x != 0) << 0) | ((unsigned)(ib.y != 0) << 1)
        | ((unsigned)(ib.z != 0) << 2) | ((unsigned)(ib.w != 0) << 3);

    const int   m  = __ldg(mask_size + s);
    const float mv = (float)__ldg(mask_value);

    // ---- local "last start index" per half, packed s16x2 (a=hi, b=lo) ----
    int la = bitsa ? (t0a + 31 - __clz(bitsa)) : -1;   // [-1, 2047]
    int lb = bitsb ? (t0b + 31 - __clz(bitsb)) : -1;   // [-1, 4095]
    unsigned p = ((unsigned)(la & 0xFFFF) << 16) | (unsigned)(lb & 0xFFFF);

    // ---- single packed block-wide max-scan ----
    #pragma unroll
    for (int off = 1; off < 32; off <<= 1) {
        unsigned u = __shfl_up_sync(0xffffffffu, p, off);
        if (lane >= off) p = __vmaxs2(p, u);
    }
    __shared__ unsigned wmax[NWARP];
    if (lane == 31) wmax[wid] = p;
    __syncthreads();
    unsigned incl_prev = __shfl_up_sync(0xffffffffu, p, 1);
    unsigned excl = (lane == 0) ? 0xFFFFFFFFu : incl_prev;  // (-1,-1)
    int tot_a = -1;                           // block-wide max of first half
    #pragma unroll
    for (int w = 0; w < NWARP; w++) {
        unsigned wm = wmax[w];
        if (w < wid) excl = __vmaxs2(excl, wm);
        tot_a = max(tot_a, (int)((short)(wm >> 16)));
    }
    int excl_a = (int)((short)(excl >> 16));
    int excl_b = max((int)((short)(excl & 0xFFFF)), tot_a);

    // ---- compute out / mask for both halves ----
    float4 oa, ob, ma, mb;
    {
        const float* xp = (const float*)&xa;
        float* op = (float*)&oa; float* mp = (float*)&ma;
        int cur = excl_a;
        #pragma unroll
        for (int i = 0; i < 4; i++) {
            int t = t0a + i;
            if ((bitsa >> i) & 1u) cur = t;
            int lo = t - m; if (lo < 0) lo = 0;
            bool msk = (cur >= lo);
            mp[i] = msk ? 1.0f : 0.0f;
            op[i] = msk ? mv : xp[i];
        }
    }
    {
        const float* xp = (const float*)&xb;
        float* op = (float*)&ob; float* mp = (float*)&mb;
        int cur = excl_b;
        #pragma unroll
        for (int i = 0; i < 4; i++) {
            int t = t0b + i;
            if ((bitsb >> i) & 1u) cur = t;
            int lo = t - m; if (lo < 0) lo = 0;
            bool msk = (cur >= lo);
            mp[i] = msk ? 1.0f : 0.0f;
            op[i] = msk ? mv : xp[i];
        }
    }

    // ---- grouped, fully-coalesced streaming stores ----
    __stcs((float4*)(out + base + t0a), oa);
    __stcs((float4*)(out + base + t0b), ob);
    if (mask_out) {
        __stcs((float4*)(mask_out + base + t0a), ma);
        __stcs((float4*)(mask_out + base + t0b), mb);
    }
}

extern "C" void kernel_launch(void* const* d_in, const int* in_sizes, int n_in,
                              void* d_out, int out_size) {
    const float* x     = (const float*)d_in[0];
    const int*   idx   = (const int*)d_in[1];
    const int*   msize = (const int*)d_in[2];
    const int*   mval  = (const int*)d_in[3];
    float* out = (float*)d_out;

    const int T = 4096;
    const int N = in_sizes[0];          // B*S*T
    const int S = in_sizes[2];          // 128
    const int rows = N / T;             // B*S = 8192

    // Tuple output (out, mask) -> concatenated float32 if out_size covers both.
    float* mask_out = (out_size >= 2 * N) ? (out + (long long)N) : nullptr;

    seg_mask_kernel<<<rows, TPB>>>(x, idx, msize, mval, out, mask_out, S, T);
}